// round 1
// baseline (speedup 1.0000x reference)
#include <cuda_runtime.h>
#include <cuda_bf16.h>

// Problem constants
#define BATCH 128
#define BINS 128
#define HW 262144               // 512*512 elements per batch (C=1)
#define TOTAL (BATCH * HW)      // 33554432
#define HIST_BPB 4              // histogram blocks per batch
#define HIST_THREADS 128
#define CHUNK (HW / HIST_BPB)   // 65536 elements per hist block

// Scratch (device globals: no allocations allowed)
__device__ int   g_hist[BATCH * BINS];
__device__ float g_w[BATCH];

// ---------------------------------------------------------------------------
// Kernel 0: zero the global histogram
// ---------------------------------------------------------------------------
__global__ void zero_hist_kernel() {
    int i = blockIdx.x * blockDim.x + threadIdx.x;
    if (i < BATCH * BINS) g_hist[i] = 0;
}

// ---------------------------------------------------------------------------
// Kernel 1: per-batch histogram.
// Per-LANE private uint16 histograms in shared memory -> zero atomics in the
// hot loop. 128 threads/block * 128 bins * 2B = 32 KB smem. Each thread
// processes CHUNK/HIST_THREADS = 512 elements (uint16 safe).
// ---------------------------------------------------------------------------
__global__ void __launch_bounds__(HIST_THREADS) hist_kernel(const float* __restrict__ x) {
    __shared__ unsigned short sh[HIST_THREADS * BINS];   // 32 KB

    unsigned short* my = sh + threadIdx.x * BINS;
    // zero private histogram (64 x 4B stores)
    #pragma unroll
    for (int i = 0; i < BINS / 2; i++)
        reinterpret_cast<unsigned int*>(my)[i] = 0u;

    const int batch = blockIdx.x >> 2;        // / HIST_BPB
    const int part  = blockIdx.x & (HIST_BPB - 1);

    const float4* xp = reinterpret_cast<const float4*>(x)
                     + (size_t)batch * (HW / 4) + (size_t)part * (CHUNK / 4);

    // CHUNK/4 = 16384 float4 per block, 128 threads -> 128 iterations
    #pragma unroll 2
    for (int i = threadIdx.x; i < CHUNK / 4; i += HIST_THREADS) {
        float4 v = xp[i];
        {
            float f = v.x;
            int bin = __float2int_rd(f * 128.0f);
            bin = min(max(bin, 0), BINS - 1);
            if (f >= 0.0f && f <= 1.0f) my[bin]++;
        }
        {
            float f = v.y;
            int bin = __float2int_rd(f * 128.0f);
            bin = min(max(bin, 0), BINS - 1);
            if (f >= 0.0f && f <= 1.0f) my[bin]++;
        }
        {
            float f = v.z;
            int bin = __float2int_rd(f * 128.0f);
            bin = min(max(bin, 0), BINS - 1);
            if (f >= 0.0f && f <= 1.0f) my[bin]++;
        }
        {
            float f = v.w;
            int bin = __float2int_rd(f * 128.0f);
            bin = min(max(bin, 0), BINS - 1);
            if (f >= 0.0f && f <= 1.0f) my[bin]++;
        }
    }
    __syncthreads();

    // Reduce the 128 private copies. Thread t owns bin t.
    // Column read: addr = c*256B + t*2B -> bank ((t>>1)&31) fixed per thread,
    // distinct (word-level) across a warp -> conflict-free.
    const int t = threadIdx.x;
    int sum = 0;
    #pragma unroll 8
    for (int c = 0; c < HIST_THREADS; c++)
        sum += (int)sh[c * BINS + t];

    atomicAdd(&g_hist[batch * BINS + t], sum);
}

// ---------------------------------------------------------------------------
// Kernel 2: tiny MLP. One block, 128 threads; thread b handles batch b.
//   h = relu(hist[b] @ W1 + b1)   (128x16)
//   w = h @ W2 + b2               (16x1)
// ---------------------------------------------------------------------------
__global__ void __launch_bounds__(BATCH) mlp_kernel(const float* __restrict__ W1,
                                                    const float* __restrict__ b1,
                                                    const float* __restrict__ W2,
                                                    const float* __restrict__ b2) {
    const int b = threadIdx.x;
    float h[16];
    #pragma unroll
    for (int j = 0; j < 16; j++) h[j] = b1[j];

    #pragma unroll 4
    for (int k = 0; k < BINS; k++) {
        float c = (float)g_hist[b * BINS + k];
        #pragma unroll
        for (int j = 0; j < 16; j++)
            h[j] = fmaf(c, W1[k * 16 + j], h[j]);
    }

    float w = b2[0];
    #pragma unroll
    for (int j = 0; j < 16; j++)
        w = fmaf(fmaxf(h[j], 0.0f), W2[j], w);

    g_w[b] = w;
}

// ---------------------------------------------------------------------------
// Kernel 3: out = x * w[batch]. float4 vectorized; 65536 float4 per batch so
// batch = vec_idx >> 16 (warp-uniform).
// ---------------------------------------------------------------------------
__global__ void __launch_bounds__(256) scale_kernel(const float* __restrict__ x,
                                                    float* __restrict__ out) {
    size_t vi = (size_t)blockIdx.x * blockDim.x + threadIdx.x;
    float w = g_w[vi >> 16];
    float4 v = reinterpret_cast<const float4*>(x)[vi];
    v.x *= w; v.y *= w; v.z *= w; v.w *= w;
    reinterpret_cast<float4*>(out)[vi] = v;
}

// ---------------------------------------------------------------------------
// Launch
// ---------------------------------------------------------------------------
extern "C" void kernel_launch(void* const* d_in, const int* in_sizes, int n_in,
                              void* d_out, int out_size) {
    const float* x  = (const float*)d_in[0];
    const float* W1 = (const float*)d_in[1];
    const float* b1 = (const float*)d_in[2];
    const float* W2 = (const float*)d_in[3];
    const float* b2 = (const float*)d_in[4];
    float* out = (float*)d_out;

    zero_hist_kernel<<<(BATCH * BINS + 255) / 256, 256>>>();
    hist_kernel<<<BATCH * HIST_BPB, HIST_THREADS>>>(x);
    mlp_kernel<<<1, BATCH>>>(W1, b1, W2, b2);
    scale_kernel<<<(TOTAL / 4) / 256, 256>>>(x, out);
}